// round 17
// baseline (speedup 1.0000x reference)
#include <cuda_runtime.h>
#include <cuda_fp16.h>
#include <cstdint>

#define Z_STRIDE 272                      // 128 fp16 + 16B pad; 272%128==16 -> conflict-free
#define Z_BYTES  (256 * Z_STRIDE)         // 69632
#define OFF_P    Z_BYTES                  // per-row partial sums: 256 x float2 = 2048 B
#define SMEM_TOTAL (Z_BYTES + 2048)       // 71680 B -> 2 CTAs/SM

__device__ uint32_t g_wfrag[32768];       // A fragments: [wb(8)][lane(32)][fi(128)]

__device__ __forceinline__ uint32_t s2u(const void* p){
    uint32_t a;
    asm("{ .reg .u64 t; cvta.to.shared.u64 t, %1; cvt.u32.u64 %0, t; }" : "=r"(a) : "l"(p));
    return a;
}
__device__ __forceinline__ void cluster_sync(){
    asm volatile("barrier.cluster.arrive.aligned;" ::: "memory");
    asm volatile("barrier.cluster.wait.aligned;" ::: "memory");
}

// ---------------- weight prep (A fragments for mma.sync) ----------------
__global__ void __launch_bounds__(256) prep_weights(const float* __restrict__ cw){
    const int idx = blockIdx.x * 256 + threadIdx.x;      // 32768
    int wb = idx >> 12;
    int ln = (idx >> 7) & 31;
    int fi = idx & 127;
    int kt = fi >> 3, mt = (fi >> 2) & 1, j = fi & 3;
    int o = wb * 32 + mt * 16 + (ln >> 2) + (j & 1) * 8;
    int c = kt * 16 + (ln & 3) * 2 + (j >> 1) * 8;
    float2 wv = *(const float2*)(cw + o * 256 + c);
    __half2 hw = __floats2half2_rn(wv.x, wv.y);
    g_wfrag[idx] = *(uint32_t*)&hw;
}

// ---------------- fused kernel: 2-CTA cluster per (b, h); each CTA owns a w-half ----------------
__global__ void __launch_bounds__(256, 2) __cluster_dims__(2, 1, 1)
fused_ln_conv_relu(const float* __restrict__ x, const float* __restrict__ y,
                   const float* __restrict__ lnw, const float* __restrict__ lnb,
                   float* __restrict__ out)
{
    extern __shared__ __align__(128) char smem[];
    const uint32_t su = s2u(smem);
    const int tid = threadIdx.x, wid = tid >> 5, lane = tid & 31;
    const int whalf = blockIdx.x & 1;                    // cluster rank
    const int pid = blockIdx.x >> 1;
    const int b = pid >> 8, h = pid & 255;
    const size_t base_bh = ((size_t)b << 24) + ((size_t)h << 8) + whalf * 128;

    // LN params for this CTA's w-half (w = whalf*128 + 4*lane + j)
    const float4 lw = *(const float4*)(lnw + whalf * 128 + 4 * lane);
    const float4 lb = *(const float4*)(lnb + whalf * 128 + 4 * lane);

    // ---- phase 1: LN with cross-CTA stat exchange; 32 rows/warp in 4 batches of 8 ----
    {
        const uint32_t peer = (uint32_t)(whalf ^ 1);
        #pragma unroll 1
        for (int bat = 0; bat < 4; bat++) {
            float4 v[8];
            float sl[8], ql[8];
            #pragma unroll
            for (int r = 0; r < 8; r++) {
                const int c = wid * 32 + bat * 8 + r;
                const float4 xa = *(const float4*)(x + base_bh + ((size_t)c << 16) + 4 * lane);
                const float4 ya = *(const float4*)(y + base_bh + ((size_t)c << 16) + 4 * lane);
                v[r].x = xa.x + ya.x; v[r].y = xa.y + ya.y;
                v[r].z = xa.z + ya.z; v[r].w = xa.w + ya.w;
                float s = v[r].x + v[r].y + v[r].z + v[r].w;
                float q = v[r].x*v[r].x + v[r].y*v[r].y + v[r].z*v[r].z + v[r].w*v[r].w;
                #pragma unroll
                for (int o_ = 16; o_; o_ >>= 1) {
                    s += __shfl_xor_sync(0xFFFFFFFFu, s, o_);
                    q += __shfl_xor_sync(0xFFFFFFFFu, q, o_);
                }
                sl[r] = s; ql[r] = q;
                if (lane == 0)
                    *(float2*)(smem + OFF_P + c * 8) = make_float2(s, q);
            }
            cluster_sync();                              // partials visible cluster-wide
            #pragma unroll
            for (int r = 0; r < 8; r++) {
                const int c = wid * 32 + bat * 8 + r;
                uint32_t rem;
                asm("mapa.shared::cluster.u32 %0, %1, %2;"
                    : "=r"(rem) : "r"(su + OFF_P + (uint32_t)(c * 8)), "r"(peer));
                float ps, pq;
                asm volatile("ld.shared::cluster.v2.f32 {%0,%1}, [%2];"
                             : "=f"(ps), "=f"(pq) : "r"(rem));
                const float mean = (sl[r] + ps) * (1.0f / 256.0f);
                const float var  = (ql[r] + pq) * (1.0f / 256.0f) - mean * mean;
                const float rstd = rsqrtf(var + 1e-5f);
                __half2 h01 = __floats2half2_rn((v[r].x - mean) * rstd * lw.x + lb.x,
                                                (v[r].y - mean) * rstd * lw.y + lb.y);
                __half2 h23 = __floats2half2_rn((v[r].z - mean) * rstd * lw.z + lb.z,
                                                (v[r].w - mean) * rstd * lw.w + lb.w);
                *(uint2*)(smem + c * Z_STRIDE + 8 * lane) =
                    make_uint2(*(uint32_t*)&h01, *(uint32_t*)&h23);
            }
        }
    }
    __syncthreads();

    // ---- phase 2: GEMM D[o, w-half] = sum_c W[o,c] * Z[c,w]; R7's inner shape, 2 wc ----
    const uint4* wf = (const uint4*)g_wfrag + ((wid * 32 + lane) * 32);
    const int g = lane >> 2, t = lane & 3;
    const uint32_t krow_off = ((uint32_t)((lane >> 3) & 1)) * 8 + (lane & 7);
    const uint32_t ncol_off = ((uint32_t)(lane >> 4)) * 8;
    float* outp = out + ((size_t)b << 24) + ((size_t)(wid * 32 + g) << 16) + ((size_t)h << 8)
                      + whalf * 128;

    #pragma unroll 1
    for (int wc = 0; wc < 2; wc++) {                 // w-chunks of 64 within the 128 half
        float acc[2][8][4] = {};
        #pragma unroll 2
        for (int kt = 0; kt < 16; kt++) {
            uint4 a0 = __ldg(wf + kt * 2);
            uint4 a1 = __ldg(wf + kt * 2 + 1);
            uint32_t bf[8][2];
            #pragma unroll
            for (int qq = 0; qq < 4; qq++) {
                uint32_t addr = su + (kt * 16 + krow_off) * Z_STRIDE
                                   + (uint32_t)(wc * 64 + qq * 16) * 2 + ncol_off * 2;
                asm volatile("ldmatrix.sync.aligned.m8n8.x4.trans.shared.b16 {%0,%1,%2,%3}, [%4];"
                             : "=r"(bf[2*qq][0]), "=r"(bf[2*qq][1]),
                               "=r"(bf[2*qq+1][0]), "=r"(bf[2*qq+1][1])
                             : "r"(addr));
            }
            #pragma unroll
            for (int nt = 0; nt < 8; nt++) {
                asm volatile(
                    "mma.sync.aligned.m16n8k16.row.col.f32.f16.f16.f32 "
                    "{%0,%1,%2,%3}, {%4,%5,%6,%7}, {%8,%9}, {%0,%1,%2,%3};"
                    : "+f"(acc[0][nt][0]), "+f"(acc[0][nt][1]), "+f"(acc[0][nt][2]), "+f"(acc[0][nt][3])
                    : "r"(a0.x), "r"(a0.y), "r"(a0.z), "r"(a0.w),
                      "r"(bf[nt][0]), "r"(bf[nt][1]));
                asm volatile(
                    "mma.sync.aligned.m16n8k16.row.col.f32.f16.f16.f32 "
                    "{%0,%1,%2,%3}, {%4,%5,%6,%7}, {%8,%9}, {%0,%1,%2,%3};"
                    : "+f"(acc[1][nt][0]), "+f"(acc[1][nt][1]), "+f"(acc[1][nt][2]), "+f"(acc[1][nt][3])
                    : "r"(a1.x), "r"(a1.y), "r"(a1.z), "r"(a1.w),
                      "r"(bf[nt][0]), "r"(bf[nt][1]));
            }
        }
        // store this w-chunk with ReLU, direct from fragments (streaming)
        #pragma unroll
        for (int mt = 0; mt < 2; mt++) {
            #pragma unroll
            for (int nt = 0; nt < 8; nt++) {
                const int w = wc * 64 + nt * 8 + t * 2;
                float* p0 = outp + ((size_t)(mt * 16) << 16) + w;
                float2 v0 = make_float2(fmaxf(acc[mt][nt][0], 0.f), fmaxf(acc[mt][nt][1], 0.f));
                float2 v1 = make_float2(fmaxf(acc[mt][nt][2], 0.f), fmaxf(acc[mt][nt][3], 0.f));
                __stcs((float2*)p0, v0);
                __stcs((float2*)(p0 + (8 << 16)), v1);   // +8 o-rows
            }
        }
    }

    // keep SMEM alive until the peer is past all DSMEM reads (symmetric, cheap)
    cluster_sync();
}

extern "C" void kernel_launch(void* const* d_in, const int* in_sizes, int n_in,
                              void* d_out, int out_size) {
    (void)in_sizes; (void)n_in; (void)out_size;
    const float* x   = (const float*)d_in[0];
    const float* y   = (const float*)d_in[1];
    const float* lnw = (const float*)d_in[2];
    const float* lnb = (const float*)d_in[3];
    const float* cw  = (const float*)d_in[4];
    float* out = (float*)d_out;

    cudaFuncSetAttribute(fused_ln_conv_relu, cudaFuncAttributeMaxDynamicSharedMemorySize, SMEM_TOTAL);

    prep_weights<<<128, 256>>>(cw);
    fused_ln_conv_relu<<<2048, 256, SMEM_TOTAL>>>(x, y, lnw, lnb, out);
}